// round 1
// baseline (speedup 1.0000x reference)
#include <cuda_runtime.h>
#include <cuda_bf16.h>
#include <math.h>

// Problem constants
#define Bv 8
#define Tv 1024
#define Cv 16
#define Lv 1040      // C + T
#define Dv 512
#define Hv 8
#define DHv 64
#define NLv 2
#define DFFv 2048
#define VSv 8000     // V*S
#define Sv 8

// ---------------- scratch (static device globals; allocation-free) ----------
__device__ float g_X  [Bv * Lv * Dv];          // running activations
__device__ float g_MEM[Bv * Lv * Dv];          // cross-attn memory (initial x)
__device__ float g_Q  [Bv * Lv * Dv];          // Q projection [B*L, 512]
__device__ float g_KV [Bv * Lv * 2 * Dv];      // K|V projection [B*L, 1024]
__device__ float g_Qt [Bv * Hv * Lv * DHv];    // [bh, L, 64]
__device__ float g_Kt [Bv * Hv * Lv * DHv];
__device__ float g_Vt [Bv * Hv * Lv * DHv];
__device__ float g_att[(long)Bv * Hv * Lv * Lv]; // [bh, L, L]  ~277MB
__device__ float g_ctxT[Bv * Hv * Lv * DHv];
__device__ float g_ctx[Bv * Lv * Dv];
__device__ float g_Y  [Bv * Lv * Dv];          // sublayer output before LN
__device__ float g_Hff[Bv * Lv * DFFv];        // FFN hidden

// ---------------- embed: x = concat(prefix, gather(emb)) + pos --------------
__global__ __launch_bounds__(256) void embed_kernel(
    const int* __restrict__ token, const int* __restrict__ state,
    const float* __restrict__ prefix, const float* __restrict__ emb,
    const float* __restrict__ b_in, const float* __restrict__ pos,
    float* __restrict__ X, float* __restrict__ MEM)
{
    long i = (long)blockIdx.x * 256 + threadIdx.x;
    if (i >= (long)Bv * Lv * Dv) return;
    int d = (int)(i & (Dv - 1));
    long r = i >> 9;               // /512
    int l = (int)(r % Lv);
    int b = (int)(r / Lv);
    float v;
    if (l < Cv) {
        v = prefix[((long)b * Cv + l) * Dv + d];
    } else {
        int t = l - Cv;
        int row = token[b * Tv + t] * Sv + state[b];
        v = emb[(long)row * Dv + d] + b_in[d];
    }
    v += pos[(long)l * Dv + d];
    X[i] = v;
    MEM[i] = v;
}

// ---------------- generic tiled SGEMM: C = alpha * A * op(B) + bias ---------
// A: [M,K] lda ; B: transB ? [N,K] ldb : [K,N] ldb ; C: [M,N] ldc
// flags: bit0 = transB ; bit1 = relu
// batched over blockIdx.z via byte-element strides sA/sB/sC
#define BM 128
#define BN 128
#define BKt 16

__global__ __launch_bounds__(256) void gemm_kernel(
    const float* __restrict__ A, const float* __restrict__ Bm,
    const float* __restrict__ bias, float* __restrict__ C,
    int M, int N, int K, int lda, int ldb, int ldc,
    long sA, long sB, long sC, float alpha, int flags)
{
    __shared__ float sAe[BKt][BM];
    __shared__ float sBe[BKt][BN];
    int z = blockIdx.z;
    A  += (long)z * sA;
    Bm += (long)z * sB;
    C  += (long)z * sC;
    int m0 = blockIdx.y * BM, n0 = blockIdx.x * BN;
    int tid = threadIdx.x;
    int tx = tid & 15, ty = tid >> 4;

    float acc[8][8];
#pragma unroll
    for (int i = 0; i < 8; i++)
#pragma unroll
        for (int j = 0; j < 8; j++) acc[i][j] = 0.f;

    for (int k0 = 0; k0 < K; k0 += BKt) {
        // load A tile: s_A[k][m]
#pragma unroll
        for (int it = 0; it < 2; it++) {
            int i = tid + it * 256;
            int r = i >> 2;
            int kc = (i & 3) * 4;
            float4 v = make_float4(0.f, 0.f, 0.f, 0.f);
            if (m0 + r < M) v = *(const float4*)&A[(long)(m0 + r) * lda + k0 + kc];
            sAe[kc + 0][r] = v.x; sAe[kc + 1][r] = v.y;
            sAe[kc + 2][r] = v.z; sAe[kc + 3][r] = v.w;
        }
        if (flags & 1) {  // NT: B[n,k]
#pragma unroll
            for (int it = 0; it < 2; it++) {
                int i = tid + it * 256;
                int r = i >> 2;
                int kc = (i & 3) * 4;
                float4 v = make_float4(0.f, 0.f, 0.f, 0.f);
                if (n0 + r < N) v = *(const float4*)&Bm[(long)(n0 + r) * ldb + k0 + kc];
                sBe[kc + 0][r] = v.x; sBe[kc + 1][r] = v.y;
                sBe[kc + 2][r] = v.z; sBe[kc + 3][r] = v.w;
            }
        } else {          // NN: B[k,n]
#pragma unroll
            for (int it = 0; it < 2; it++) {
                int i = tid + it * 256;
                int kc = i >> 5;
                int nc = (i & 31) * 4;
                float4 v = make_float4(0.f, 0.f, 0.f, 0.f);
                if (n0 + nc < N) v = *(const float4*)&Bm[(long)(k0 + kc) * ldb + n0 + nc];
                *(float4*)&sBe[kc][nc] = v;
            }
        }
        __syncthreads();
#pragma unroll
        for (int kk = 0; kk < BKt; kk++) {
            float a[8], b[8];
            *(float4*)&a[0] = *(const float4*)&sAe[kk][ty * 8];
            *(float4*)&a[4] = *(const float4*)&sAe[kk][ty * 8 + 4];
            *(float4*)&b[0] = *(const float4*)&sBe[kk][tx * 8];
            *(float4*)&b[4] = *(const float4*)&sBe[kk][tx * 8 + 4];
#pragma unroll
            for (int i = 0; i < 8; i++)
#pragma unroll
                for (int j = 0; j < 8; j++)
                    acc[i][j] += a[i] * b[j];
        }
        __syncthreads();
    }
    // epilogue
#pragma unroll
    for (int i = 0; i < 8; i++) {
        int row = m0 + ty * 8 + i;
        if (row >= M) continue;
#pragma unroll
        for (int jg = 0; jg < 2; jg++) {
            int col = n0 + tx * 8 + jg * 4;
            if (col >= N) continue;
            float4 o;
            float* po = (float*)&o;
#pragma unroll
            for (int q = 0; q < 4; q++) {
                float v = acc[i][jg * 4 + q] * alpha;
                if (bias) v += bias[col + q];
                if (flags & 2) v = fmaxf(v, 0.f);
                po[q] = v;
            }
            *(float4*)&C[(long)row * ldc + col] = o;
        }
    }
}

// ---------------- [B,L,(H,64)] (strided cols) -> [bh, L, 64] -----------------
__global__ __launch_bounds__(256) void to_bhld_kernel(
    const float* __restrict__ in, float* __restrict__ out, int ld_in, int col0)
{
    long i = (long)blockIdx.x * 256 + threadIdx.x;
    if (i >= (long)Bv * Hv * Lv * DHv) return;
    int d = (int)(i & 63);
    long r = i >> 6;
    int l = (int)(r % Lv); r /= Lv;
    int h = (int)(r % Hv);
    int b = (int)(r / Hv);
    out[i] = in[((long)b * Lv + l) * ld_in + col0 + h * DHv + d];
}

// ---------------- [bh, L, 64] -> [B,L,512] -----------------------------------
__global__ __launch_bounds__(256) void from_bhld_kernel(
    const float* __restrict__ in, float* __restrict__ out)
{
    long i = (long)blockIdx.x * 256 + threadIdx.x;
    if (i >= (long)Bv * Lv * Dv) return;
    int d = (int)(i & 63);
    long r = i >> 6;
    int h = (int)(r & 7); r >>= 3;
    int l = (int)(r % Lv);
    int b = (int)(r / Lv);
    out[i] = in[(((long)b * Hv + h) * Lv + l) * DHv + d];
}

// ---------------- row softmax over length L ----------------------------------
__global__ __launch_bounds__(256) void softmax_kernel(float* __restrict__ att)
{
    long row = blockIdx.x;
    float* p = att + row * (long)Lv;
    int tid = threadIdx.x;
    float vals[5];
    int cnt = 0;
    float mx = -1e30f;
    for (int c = tid; c < Lv; c += 256) { vals[cnt] = p[c]; mx = fmaxf(mx, vals[cnt]); cnt++; }
    __shared__ float red[256];
    red[tid] = mx; __syncthreads();
#pragma unroll
    for (int s = 128; s > 0; s >>= 1) { if (tid < s) red[tid] = fmaxf(red[tid], red[tid + s]); __syncthreads(); }
    mx = red[0]; __syncthreads();
    float sum = 0.f;
    for (int i = 0; i < cnt; i++) { vals[i] = expf(vals[i] - mx); sum += vals[i]; }
    red[tid] = sum; __syncthreads();
#pragma unroll
    for (int s = 128; s > 0; s >>= 1) { if (tid < s) red[tid] += red[tid + s]; __syncthreads(); }
    float inv = 1.f / red[0];
    cnt = 0;
    for (int c = tid; c < Lv; c += 256) { p[c] = vals[cnt] * inv; cnt++; }
}

// ---------------- X = LayerNorm(X + Y) * g + b -------------------------------
__global__ __launch_bounds__(256) void ln_kernel(
    float* __restrict__ X, const float* __restrict__ Y,
    const float* __restrict__ g, const float* __restrict__ b)
{
    long row = blockIdx.x;
    float* x = X + row * (long)Dv;
    const float* y = Y + row * (long)Dv;
    int tid = threadIdx.x;
    float v0 = x[tid] + y[tid];
    float v1 = x[tid + 256] + y[tid + 256];
    __shared__ float red[256];
    red[tid] = v0 + v1; __syncthreads();
#pragma unroll
    for (int s = 128; s > 0; s >>= 1) { if (tid < s) red[tid] += red[tid + s]; __syncthreads(); }
    float mu = red[0] * (1.f / Dv); __syncthreads();
    float d0 = v0 - mu, d1 = v1 - mu;
    red[tid] = d0 * d0 + d1 * d1; __syncthreads();
#pragma unroll
    for (int s = 128; s > 0; s >>= 1) { if (tid < s) red[tid] += red[tid + s]; __syncthreads(); }
    float rstd = rsqrtf(red[0] * (1.f / Dv) + 1e-5f);
    x[tid]       = d0 * rstd * g[tid]       + b[tid];
    x[tid + 256] = d1 * rstd * g[tid + 256] + b[tid + 256];
}

// ---------------- host orchestration -----------------------------------------
static inline dim3 ggrid(int M, int N, int batch) {
    return dim3((N + BN - 1) / BN, (M + BM - 1) / BM, batch);
}

extern "C" void kernel_launch(void* const* d_in, const int* in_sizes, int n_in,
                              void* d_out, int out_size)
{
    const int*   token  = (const int*)  d_in[0];
    const int*   state  = (const int*)  d_in[1];
    const float* prefix = (const float*)d_in[2];
    const float* emb    = (const float*)d_in[3];
    const float* b_in   = (const float*)d_in[4];
    const float* pos    = (const float*)d_in[5];
    const float* W_out  = (const float*)d_in[6];
    const float* b_out  = (const float*)d_in[7];
    const float* qkv_w  = (const float*)d_in[8];
    const float* qkv_b  = (const float*)d_in[9];
    const float* out_w  = (const float*)d_in[10];
    const float* out_b  = (const float*)d_in[11];
    const float* lin1_w = (const float*)d_in[12];
    const float* lin1_b = (const float*)d_in[13];
    const float* lin2_w = (const float*)d_in[14];
    const float* lin2_b = (const float*)d_in[15];
    const float* ln_g   = (const float*)d_in[16];
    const float* ln_b   = (const float*)d_in[17];
    float* out = (float*)d_out;

    float *X, *MEM, *Q, *KV, *Qt, *Kt, *Vt, *att, *ctxT, *ctx, *Y, *Hff;
    cudaGetSymbolAddress((void**)&X,   g_X);
    cudaGetSymbolAddress((void**)&MEM, g_MEM);
    cudaGetSymbolAddress((void**)&Q,   g_Q);
    cudaGetSymbolAddress((void**)&KV,  g_KV);
    cudaGetSymbolAddress((void**)&Qt,  g_Qt);
    cudaGetSymbolAddress((void**)&Kt,  g_Kt);
    cudaGetSymbolAddress((void**)&Vt,  g_Vt);
    cudaGetSymbolAddress((void**)&att, g_att);
    cudaGetSymbolAddress((void**)&ctxT,g_ctxT);
    cudaGetSymbolAddress((void**)&ctx, g_ctx);
    cudaGetSymbolAddress((void**)&Y,   g_Y);
    cudaGetSymbolAddress((void**)&Hff, g_Hff);

    const int BL = Bv * Lv;                 // 8320
    const long nEmb = (long)Bv * Lv * Dv;   // 4,259,840
    const long nHead = (long)Bv * Hv * Lv * DHv;

    embed_kernel<<<(int)((nEmb + 255) / 256), 256>>>(token, state, prefix, emb, b_in, pos, X, MEM);

    const float scale = 1.f / 8.f;          // 1/sqrt(64)

    for (int i = 0; i < NLv; i++) {
        for (int j = 0; j < 2; j++) {
            const float* kvsrc = (j == 0) ? X : MEM;
            const float* w  = qkv_w + (long)(i * 2 + j) * 3 * Dv * Dv;
            const float* bb = qkv_b + (long)(i * 2 + j) * 3 * Dv;

            // Q = X @ Wq^T + bq        [8320, 512]
            gemm_kernel<<<ggrid(BL, Dv, 1), 256>>>(X, w, bb, Q,
                BL, Dv, Dv, Dv, Dv, Dv, 0, 0, 0, 1.f, 1);
            // KV = kvsrc @ [Wk;Wv]^T + b   [8320, 1024]
            gemm_kernel<<<ggrid(BL, 2 * Dv, 1), 256>>>(kvsrc, w + (long)Dv * Dv, bb + Dv, KV,
                BL, 2 * Dv, Dv, Dv, Dv, 2 * Dv, 0, 0, 0, 1.f, 1);

            to_bhld_kernel<<<(int)((nHead + 255) / 256), 256>>>(Q,  Qt, Dv, 0);
            to_bhld_kernel<<<(int)((nHead + 255) / 256), 256>>>(KV, Kt, 2 * Dv, 0);
            to_bhld_kernel<<<(int)((nHead + 255) / 256), 256>>>(KV, Vt, 2 * Dv, Dv);

            // att = scale * Qt @ Kt^T   per (b,h): [1040,1040], K=64
            gemm_kernel<<<ggrid(Lv, Lv, Bv * Hv), 256>>>(Qt, Kt, nullptr, att,
                Lv, Lv, DHv, DHv, DHv, Lv,
                (long)Lv * DHv, (long)Lv * DHv, (long)Lv * Lv, scale, 1);

            softmax_kernel<<<Bv * Hv * Lv, 256>>>(att);

            // ctxT = att @ Vt (NN)      per (b,h): [1040,64], K=1040
            gemm_kernel<<<ggrid(Lv, DHv, Bv * Hv), 256>>>(att, Vt, nullptr, ctxT,
                Lv, DHv, Lv, Lv, DHv, DHv,
                (long)Lv * Lv, (long)Lv * DHv, (long)Lv * DHv, 1.f, 0);

            from_bhld_kernel<<<(int)((nEmb + 255) / 256), 256>>>(ctxT, ctx);

            // Y = ctx @ Wo^T + bo
            gemm_kernel<<<ggrid(BL, Dv, 1), 256>>>(ctx,
                out_w + (long)(i * 2 + j) * Dv * Dv, out_b + (long)(i * 2 + j) * Dv, Y,
                BL, Dv, Dv, Dv, Dv, Dv, 0, 0, 0, 1.f, 1);

            // X = LN(X + Y)
            ln_kernel<<<BL, 256>>>(X, Y,
                ln_g + (long)(i * 3 + j) * Dv, ln_b + (long)(i * 3 + j) * Dv);
        }
        // FFN
        gemm_kernel<<<ggrid(BL, DFFv, 1), 256>>>(X,
            lin1_w + (long)i * DFFv * Dv, lin1_b + (long)i * DFFv, Hff,
            BL, DFFv, Dv, Dv, Dv, DFFv, 0, 0, 0, 1.f, 1 | 2);
        gemm_kernel<<<ggrid(BL, Dv, 1), 256>>>(Hff,
            lin2_w + (long)i * Dv * DFFv, lin2_b + (long)i * Dv, Y,
            BL, Dv, DFFv, DFFv, DFFv, Dv, 0, 0, 0, 1.f, 1);
        ln_kernel<<<BL, 256>>>(X, Y,
            ln_g + (long)(i * 3 + 2) * Dv, ln_b + (long)(i * 3 + 2) * Dv);
    }

    // logits[b, t, :] = X[b, C+t, :] @ W_out^T + b_out   (batched over b)
    gemm_kernel<<<ggrid(Tv, VSv, Bv), 256>>>(X + (long)Cv * Dv, W_out, b_out, out,
        Tv, VSv, Dv, Dv, Dv, VSv,
        (long)Lv * Dv, 0, (long)Tv * VSv, 1.f, 1);
}

// round 2
// speedup vs baseline: 2.1970x; 2.1970x over previous
#include <cuda_runtime.h>
#include <cuda_bf16.h>
#include <math.h>
#include <stdint.h>

// Problem constants
#define Bv 8
#define Tv 1024
#define Cv 16
#define Lv 1040      // C + T
#define Dv 512
#define Hv 8
#define DHv 64
#define NLv 2
#define DFFv 2048
#define VSv 8000     // V*S
#define Sv 8

// ---------------- scratch (static device globals; allocation-free) ----------
__device__ float g_X  [Bv * Lv * Dv];
__device__ float g_MEM[Bv * Lv * Dv];
__device__ float g_Q  [Bv * Lv * Dv];
__device__ float g_KV [Bv * Lv * 2 * Dv];
__device__ float g_Qt [Bv * Hv * Lv * DHv];
__device__ float g_Kt [Bv * Hv * Lv * DHv];
__device__ float g_Vt [Bv * Hv * Lv * DHv];
__device__ float g_att[(long)Bv * Hv * Lv * Lv];
__device__ float g_ctxT[Bv * Hv * Lv * DHv];
__device__ float g_ctx[Bv * Lv * Dv];
__device__ float g_Y  [Bv * Lv * Dv];
__device__ float g_Hff[Bv * Lv * DFFv];

// ---------------- embed ------------------------------------------------------
__global__ __launch_bounds__(256) void embed_kernel(
    const int* __restrict__ token, const int* __restrict__ state,
    const float* __restrict__ prefix, const float* __restrict__ emb,
    const float* __restrict__ b_in, const float* __restrict__ pos,
    float* __restrict__ X, float* __restrict__ MEM)
{
    long i = (long)blockIdx.x * 256 + threadIdx.x;
    if (i >= (long)Bv * Lv * Dv) return;
    int d = (int)(i & (Dv - 1));
    long r = i >> 9;
    int l = (int)(r % Lv);
    int b = (int)(r / Lv);
    float v;
    if (l < Cv) {
        v = prefix[((long)b * Cv + l) * Dv + d];
    } else {
        int t = l - Cv;
        int row = token[b * Tv + t] * Sv + state[b];
        v = emb[(long)row * Dv + d] + b_in[d];
    }
    v += pos[(long)l * Dv + d];
    X[i] = v;
    MEM[i] = v;
}

// ---------------- tf32 tensor-core GEMM --------------------------------------
// C = alpha * A * op(B) + bias  ; A:[M,K] lda ; B: transB? [N,K]:[K,N] ldb
// flags: bit0 = transB ; bit1 = relu. Batched via element strides sA/sB/sC.
// Tile: BM=128, BN=128, BK=16. 256 threads = 8 warps (4 M x 2 N), warp = 32x64.
#define SAS 136   // smem row stride (conflict-free: (t*136+g)%32 hits 32 banks)

__device__ __forceinline__ uint32_t f2tf32(float x) {
    uint32_t r;
    asm("cvt.rna.tf32.f32 %0, %1;" : "=r"(r) : "f"(x));
    return r;
}

__device__ __forceinline__ void mma_tf32(float* d, const uint32_t* a,
                                         uint32_t b0, uint32_t b1) {
    asm volatile(
        "mma.sync.aligned.m16n8k8.row.col.f32.tf32.tf32.f32 "
        "{%0,%1,%2,%3}, {%4,%5,%6,%7}, {%8,%9}, {%0,%1,%2,%3};\n"
        : "+f"(d[0]), "+f"(d[1]), "+f"(d[2]), "+f"(d[3])
        : "r"(a[0]), "r"(a[1]), "r"(a[2]), "r"(a[3]), "r"(b0), "r"(b1));
}

__global__ __launch_bounds__(256) void gemm_tf32_kernel(
    const float* __restrict__ A, const float* __restrict__ Bm,
    const float* __restrict__ bias, float* __restrict__ C,
    int M, int N, int K, int lda, int ldb, int ldc,
    long strA, long strB, long strC, float alpha, int flags)
{
    __shared__ uint32_t sA[16 * SAS];
    __shared__ uint32_t sB[16 * SAS];

    int z = blockIdx.z;
    A  += (long)z * strA;
    Bm += (long)z * strB;
    C  += (long)z * strC;
    int m0 = blockIdx.y * 128, n0 = blockIdx.x * 128;
    int tid = threadIdx.x;
    int warp = tid >> 5, lane = tid & 31;
    int wm = warp >> 1, wn = warp & 1;
    int g = lane >> 2, t = lane & 3;
    const bool transB = (flags & 1);

    float acc[2][8][4];
#pragma unroll
    for (int mt = 0; mt < 2; mt++)
#pragma unroll
        for (int nt = 0; nt < 8; nt++)
#pragma unroll
            for (int q = 0; q < 4; q++) acc[mt][nt][q] = 0.f;

    float4 rA[2], rB[2];
    const int nk = K >> 4;   // all K are multiples of 16

    // per-thread load coordinates (two 512-wide passes)
    int arow[2], akc[2], bkk[2], bnc[2];
#pragma unroll
    for (int it = 0; it < 2; it++) {
        int idx = tid + it * 256;
        arow[it] = idx >> 2;           // 0..127
        akc[it]  = (idx & 3) << 2;     // 0,4,8,12
        bkk[it]  = idx >> 5;           // 0..15   (NN layout)
        bnc[it]  = (idx & 31) << 2;    // 0..124
    }

    // prefetch tile 0
#pragma unroll
    for (int it = 0; it < 2; it++) {
        rA[it] = make_float4(0.f, 0.f, 0.f, 0.f);
        if (m0 + arow[it] < M)
            rA[it] = *(const float4*)&A[(long)(m0 + arow[it]) * lda + akc[it]];
        rB[it] = make_float4(0.f, 0.f, 0.f, 0.f);
        if (transB) {
            if (n0 + arow[it] < N)
                rB[it] = *(const float4*)&Bm[(long)(n0 + arow[it]) * ldb + akc[it]];
        } else {
            if (n0 + bnc[it] < N)
                rB[it] = *(const float4*)&Bm[(long)bkk[it] * ldb + n0 + bnc[it]];
        }
    }

    for (int kt = 0; kt < nk; kt++) {
        // store regs -> smem (with tf32 convert)
#pragma unroll
        for (int it = 0; it < 2; it++) {
            int r = arow[it], kc = akc[it];
            sA[(kc + 0) * SAS + r] = f2tf32(rA[it].x);
            sA[(kc + 1) * SAS + r] = f2tf32(rA[it].y);
            sA[(kc + 2) * SAS + r] = f2tf32(rA[it].z);
            sA[(kc + 3) * SAS + r] = f2tf32(rA[it].w);
            if (transB) {
                sB[(kc + 0) * SAS + r] = f2tf32(rB[it].x);
                sB[(kc + 1) * SAS + r] = f2tf32(rB[it].y);
                sB[(kc + 2) * SAS + r] = f2tf32(rB[it].z);
                sB[(kc + 3) * SAS + r] = f2tf32(rB[it].w);
            } else {
                int kk = bkk[it], nc = bnc[it];
                sB[kk * SAS + nc + 0] = f2tf32(rB[it].x);
                sB[kk * SAS + nc + 1] = f2tf32(rB[it].y);
                sB[kk * SAS + nc + 2] = f2tf32(rB[it].z);
                sB[kk * SAS + nc + 3] = f2tf32(rB[it].w);
            }
        }
        __syncthreads();

        // prefetch next tile (overlaps with the MMA work below)
        if (kt + 1 < nk) {
            long koff = (long)(kt + 1) << 4;
#pragma unroll
            for (int it = 0; it < 2; it++) {
                rA[it] = make_float4(0.f, 0.f, 0.f, 0.f);
                if (m0 + arow[it] < M)
                    rA[it] = *(const float4*)&A[(long)(m0 + arow[it]) * lda + koff + akc[it]];
                rB[it] = make_float4(0.f, 0.f, 0.f, 0.f);
                if (transB) {
                    if (n0 + arow[it] < N)
                        rB[it] = *(const float4*)&Bm[(long)(n0 + arow[it]) * ldb + koff + akc[it]];
                } else {
                    if (n0 + bnc[it] < N)
                        rB[it] = *(const float4*)&Bm[(long)(koff + bkk[it]) * ldb + n0 + bnc[it]];
                }
            }
        }

        // compute: 2 k-steps of 8
#pragma unroll
        for (int ks = 0; ks < 2; ks++) {
            int k0 = ks * 8;
            uint32_t aF[2][4];
#pragma unroll
            for (int mt = 0; mt < 2; mt++) {
                int rb = wm * 32 + mt * 16;
                aF[mt][0] = sA[(k0 + t) * SAS + rb + g];
                aF[mt][1] = sA[(k0 + t) * SAS + rb + g + 8];
                aF[mt][2] = sA[(k0 + t + 4) * SAS + rb + g];
                aF[mt][3] = sA[(k0 + t + 4) * SAS + rb + g + 8];
            }
#pragma unroll
            for (int nt = 0; nt < 8; nt++) {
                int cb = wn * 64 + nt * 8;
                uint32_t b0 = sB[(k0 + t) * SAS + cb + g];
                uint32_t b1 = sB[(k0 + t + 4) * SAS + cb + g];
                mma_tf32(acc[0][nt], aF[0], b0, b1);
                mma_tf32(acc[1][nt], aF[1], b0, b1);
            }
        }
        __syncthreads();
    }

    // epilogue
    const bool relu = (flags & 2);
#pragma unroll
    for (int mt = 0; mt < 2; mt++) {
        int row0 = m0 + wm * 32 + mt * 16 + g;
        int row1 = row0 + 8;
#pragma unroll
        for (int nt = 0; nt < 8; nt++) {
            int col = n0 + wn * 64 + nt * 8 + t * 2;
            if (col >= N) continue;      // N is even, col is even -> col+1 < N too
            float b0 = 0.f, b1 = 0.f;
            if (bias) { b0 = bias[col]; b1 = bias[col + 1]; }
            if (row0 < M) {
                float v0 = acc[mt][nt][0] * alpha + b0;
                float v1 = acc[mt][nt][1] * alpha + b1;
                if (relu) { v0 = fmaxf(v0, 0.f); v1 = fmaxf(v1, 0.f); }
                *(float2*)&C[(long)row0 * ldc + col] = make_float2(v0, v1);
            }
            if (row1 < M) {
                float v0 = acc[mt][nt][2] * alpha + b0;
                float v1 = acc[mt][nt][3] * alpha + b1;
                if (relu) { v0 = fmaxf(v0, 0.f); v1 = fmaxf(v1, 0.f); }
                *(float2*)&C[(long)row1 * ldc + col] = make_float2(v0, v1);
            }
        }
    }
}

// ---------------- transposes -------------------------------------------------
__global__ __launch_bounds__(256) void to_bhld_kernel(
    const float* __restrict__ in, float* __restrict__ out, int ld_in, int col0)
{
    long i = (long)blockIdx.x * 256 + threadIdx.x;
    if (i >= (long)Bv * Hv * Lv * DHv) return;
    int d = (int)(i & 63);
    long r = i >> 6;
    int l = (int)(r % Lv); r /= Lv;
    int h = (int)(r % Hv);
    int b = (int)(r / Hv);
    out[i] = in[((long)b * Lv + l) * ld_in + col0 + h * DHv + d];
}

__global__ __launch_bounds__(256) void from_bhld_kernel(
    const float* __restrict__ in, float* __restrict__ out)
{
    long i = (long)blockIdx.x * 256 + threadIdx.x;
    if (i >= (long)Bv * Lv * Dv) return;
    int d = (int)(i & 63);
    long r = i >> 6;
    int h = (int)(r & 7); r >>= 3;
    int l = (int)(r % Lv);
    int b = (int)(r / Lv);
    out[i] = in[(((long)b * Hv + h) * Lv + l) * DHv + d];
}

// ---------------- softmax ------------------------------------------------------
__global__ __launch_bounds__(256) void softmax_kernel(float* __restrict__ att)
{
    long row = blockIdx.x;
    float* p = att + row * (long)Lv;
    int tid = threadIdx.x;
    float vals[5];
    int cnt = 0;
    float mx = -1e30f;
    for (int c = tid; c < Lv; c += 256) { vals[cnt] = p[c]; mx = fmaxf(mx, vals[cnt]); cnt++; }
    __shared__ float red[256];
    red[tid] = mx; __syncthreads();
#pragma unroll
    for (int s = 128; s > 0; s >>= 1) { if (tid < s) red[tid] = fmaxf(red[tid], red[tid + s]); __syncthreads(); }
    mx = red[0]; __syncthreads();
    float sum = 0.f;
    for (int i = 0; i < cnt; i++) { vals[i] = expf(vals[i] - mx); sum += vals[i]; }
    red[tid] = sum; __syncthreads();
#pragma unroll
    for (int s = 128; s > 0; s >>= 1) { if (tid < s) red[tid] += red[tid + s]; __syncthreads(); }
    float inv = 1.f / red[0];
    cnt = 0;
    for (int c = tid; c < Lv; c += 256) { p[c] = vals[cnt] * inv; cnt++; }
}

// ---------------- residual + LayerNorm ----------------------------------------
__global__ __launch_bounds__(256) void ln_kernel(
    float* __restrict__ X, const float* __restrict__ Y,
    const float* __restrict__ g, const float* __restrict__ b)
{
    long row = blockIdx.x;
    float* x = X + row * (long)Dv;
    const float* y = Y + row * (long)Dv;
    int tid = threadIdx.x;
    float v0 = x[tid] + y[tid];
    float v1 = x[tid + 256] + y[tid + 256];
    __shared__ float red[256];
    red[tid] = v0 + v1; __syncthreads();
#pragma unroll
    for (int s = 128; s > 0; s >>= 1) { if (tid < s) red[tid] += red[tid + s]; __syncthreads(); }
    float mu = red[0] * (1.f / Dv); __syncthreads();
    float d0 = v0 - mu, d1 = v1 - mu;
    red[tid] = d0 * d0 + d1 * d1; __syncthreads();
#pragma unroll
    for (int s = 128; s > 0; s >>= 1) { if (tid < s) red[tid] += red[tid + s]; __syncthreads(); }
    float rstd = rsqrtf(red[0] * (1.f / Dv) + 1e-5f);
    x[tid]       = d0 * rstd * g[tid]       + b[tid];
    x[tid + 256] = d1 * rstd * g[tid + 256] + b[tid + 256];
}

// ---------------- host orchestration -----------------------------------------
static inline dim3 ggrid(int M, int N, int batch) {
    return dim3((N + 127) / 128, (M + 127) / 128, batch);
}

extern "C" void kernel_launch(void* const* d_in, const int* in_sizes, int n_in,
                              void* d_out, int out_size)
{
    const int*   token  = (const int*)  d_in[0];
    const int*   state  = (const int*)  d_in[1];
    const float* prefix = (const float*)d_in[2];
    const float* emb    = (const float*)d_in[3];
    const float* b_in   = (const float*)d_in[4];
    const float* pos    = (const float*)d_in[5];
    const float* W_out  = (const float*)d_in[6];
    const float* b_out  = (const float*)d_in[7];
    const float* qkv_w  = (const float*)d_in[8];
    const float* qkv_b  = (const float*)d_in[9];
    const float* out_w  = (const float*)d_in[10];
    const float* out_b  = (const float*)d_in[11];
    const float* lin1_w = (const float*)d_in[12];
    const float* lin1_b = (const float*)d_in[13];
    const float* lin2_w = (const float*)d_in[14];
    const float* lin2_b = (const float*)d_in[15];
    const float* ln_g   = (const float*)d_in[16];
    const float* ln_b   = (const float*)d_in[17];
    float* out = (float*)d_out;

    float *X, *MEM, *Q, *KV, *Qt, *Kt, *Vt, *att, *ctxT, *ctx, *Y, *Hff;
    cudaGetSymbolAddress((void**)&X,   g_X);
    cudaGetSymbolAddress((void**)&MEM, g_MEM);
    cudaGetSymbolAddress((void**)&Q,   g_Q);
    cudaGetSymbolAddress((void**)&KV,  g_KV);
    cudaGetSymbolAddress((void**)&Qt,  g_Qt);
    cudaGetSymbolAddress((void**)&Kt,  g_Kt);
    cudaGetSymbolAddress((void**)&Vt,  g_Vt);
    cudaGetSymbolAddress((void**)&att, g_att);
    cudaGetSymbolAddress((void**)&ctxT,g_ctxT);
    cudaGetSymbolAddress((void**)&ctx, g_ctx);
    cudaGetSymbolAddress((void**)&Y,   g_Y);
    cudaGetSymbolAddress((void**)&Hff, g_Hff);

    const int BL = Bv * Lv;
    const long nEmb = (long)Bv * Lv * Dv;
    const long nHead = (long)Bv * Hv * Lv * DHv;

    embed_kernel<<<(int)((nEmb + 255) / 256), 256>>>(token, state, prefix, emb, b_in, pos, X, MEM);

    const float scale = 1.f / 8.f;

    for (int i = 0; i < NLv; i++) {
        for (int j = 0; j < 2; j++) {
            const float* kvsrc = (j == 0) ? X : MEM;
            const float* w  = qkv_w + (long)(i * 2 + j) * 3 * Dv * Dv;
            const float* bb = qkv_b + (long)(i * 2 + j) * 3 * Dv;

            gemm_tf32_kernel<<<ggrid(BL, Dv, 1), 256>>>(X, w, bb, Q,
                BL, Dv, Dv, Dv, Dv, Dv, 0, 0, 0, 1.f, 1);
            gemm_tf32_kernel<<<ggrid(BL, 2 * Dv, 1), 256>>>(kvsrc, w + (long)Dv * Dv, bb + Dv, KV,
                BL, 2 * Dv, Dv, Dv, Dv, 2 * Dv, 0, 0, 0, 1.f, 1);

            to_bhld_kernel<<<(int)((nHead + 255) / 256), 256>>>(Q,  Qt, Dv, 0);
            to_bhld_kernel<<<(int)((nHead + 255) / 256), 256>>>(KV, Kt, 2 * Dv, 0);
            to_bhld_kernel<<<(int)((nHead + 255) / 256), 256>>>(KV, Vt, 2 * Dv, Dv);

            gemm_tf32_kernel<<<ggrid(Lv, Lv, Bv * Hv), 256>>>(Qt, Kt, nullptr, att,
                Lv, Lv, DHv, DHv, DHv, Lv,
                (long)Lv * DHv, (long)Lv * DHv, (long)Lv * Lv, scale, 1);

            softmax_kernel<<<Bv * Hv * Lv, 256>>>(att);

            gemm_tf32_kernel<<<ggrid(Lv, DHv, Bv * Hv), 256>>>(att, Vt, nullptr, ctxT,
                Lv, DHv, Lv, Lv, DHv, DHv,
                (long)Lv * Lv, (long)Lv * DHv, (long)Lv * DHv, 1.f, 0);

            from_bhld_kernel<<<(int)((nEmb + 255) / 256), 256>>>(ctxT, ctx);

            gemm_tf32_kernel<<<ggrid(BL, Dv, 1), 256>>>(ctx,
                out_w + (long)(i * 2 + j) * Dv * Dv, out_b + (long)(i * 2 + j) * Dv, Y,
                BL, Dv, Dv, Dv, Dv, Dv, 0, 0, 0, 1.f, 1);

            ln_kernel<<<BL, 256>>>(X, Y,
                ln_g + (long)(i * 3 + j) * Dv, ln_b + (long)(i * 3 + j) * Dv);
        }
        gemm_tf32_kernel<<<ggrid(BL, DFFv, 1), 256>>>(X,
            lin1_w + (long)i * DFFv * Dv, lin1_b + (long)i * DFFv, Hff,
            BL, DFFv, Dv, Dv, Dv, DFFv, 0, 0, 0, 1.f, 1 | 2);
        gemm_tf32_kernel<<<ggrid(BL, Dv, 1), 256>>>(Hff,
            lin2_w + (long)i * Dv * DFFv, lin2_b + (long)i * Dv, Y,
            BL, Dv, DFFv, DFFv, DFFv, Dv, 0, 0, 0, 1.f, 1);
        ln_kernel<<<BL, 256>>>(X, Y,
            ln_g + (long)(i * 3 + 2) * Dv, ln_b + (long)(i * 3 + 2) * Dv);
    }

    gemm_tf32_kernel<<<ggrid(Tv, VSv, Bv), 256>>>(X + (long)Cv * Dv, W_out, b_out, out,
        Tv, VSv, Dv, Dv, Dv, VSv,
        (long)Lv * Dv, 0, (long)Tv * VSv, 1.f, 1);
}

// round 3
// speedup vs baseline: 2.2146x; 1.0080x over previous
#include <cuda_runtime.h>
#include <cuda_bf16.h>
#include <math.h>
#include <stdint.h>

// Problem constants
#define Bv 8
#define Tv 1024
#define Cv 16
#define Lv 1040      // C + T
#define Dv 512
#define Hv 8
#define DHv 64
#define NLv 2
#define DFFv 2048
#define VSv 8000     // V*S
#define Sv 8

// ---------------- scratch (static device globals; allocation-free) ----------
__device__ float g_X  [Bv * Lv * Dv];
__device__ float g_MEM[Bv * Lv * Dv];
__device__ float g_Q  [Bv * Lv * Dv];
__device__ float g_KV [Bv * Lv * 2 * Dv];
__device__ float g_Qt [Bv * Hv * Lv * DHv];
__device__ float g_Kt [Bv * Hv * Lv * DHv];
__device__ float g_Vt [Bv * Hv * Lv * DHv];
__device__ float g_att[(long)Bv * Hv * Lv * Lv];
__device__ float g_ctxT[Bv * Hv * Lv * DHv];
__device__ float g_ctx[Bv * Lv * Dv];
__device__ float g_Y  [Bv * Lv * Dv];
__device__ float g_Hff[Bv * Lv * DFFv];

// ---------------- embed ------------------------------------------------------
__global__ __launch_bounds__(256) void embed_kernel(
    const int* __restrict__ token, const int* __restrict__ state,
    const float* __restrict__ prefix, const float* __restrict__ emb,
    const float* __restrict__ b_in, const float* __restrict__ pos,
    float* __restrict__ X, float* __restrict__ MEM)
{
    long i = (long)blockIdx.x * 256 + threadIdx.x;
    if (i >= (long)Bv * Lv * Dv) return;
    int d = (int)(i & (Dv - 1));
    long r = i >> 9;
    int l = (int)(r % Lv);
    int b = (int)(r / Lv);
    float v;
    if (l < Cv) {
        v = prefix[((long)b * Cv + l) * Dv + d];
    } else {
        int t = l - Cv;
        int row = token[b * Tv + t] * Sv + state[b];
        v = emb[(long)row * Dv + d] + b_in[d];
    }
    v += pos[(long)l * Dv + d];
    X[i] = v;
    MEM[i] = v;
}

// ---------------- tf32 tensor-core GEMM --------------------------------------
// C = alpha * A * op(B) + bias  ; A:[M,K] lda ; B: transB? [N,K]:[K,N] ldb
// flags: bit0 = transB ; bit1 = relu. Batched via element strides sA/sB/sC.
// Tile: BM=128, BN=128, BK=16. 256 threads = 8 warps (4 M x 2 N), warp = 32x64.
#define SAS 136   // smem row stride (conflict-free: (t*136+g)%32 hits 32 banks)

__device__ __forceinline__ uint32_t f2tf32(float x) {
    uint32_t r;
    asm("cvt.rna.tf32.f32 %0, %1;" : "=r"(r) : "f"(x));
    return r;
}

__device__ __forceinline__ void mma_tf32(float* d, const uint32_t* a,
                                         uint32_t b0, uint32_t b1) {
    asm volatile(
        "mma.sync.aligned.m16n8k8.row.col.f32.tf32.tf32.f32 "
        "{%0,%1,%2,%3}, {%4,%5,%6,%7}, {%8,%9}, {%0,%1,%2,%3};\n"
        : "+f"(d[0]), "+f"(d[1]), "+f"(d[2]), "+f"(d[3])
        : "r"(a[0]), "r"(a[1]), "r"(a[2]), "r"(a[3]), "r"(b0), "r"(b1));
}

__global__ __launch_bounds__(256) void gemm_tf32_kernel(
    const float* __restrict__ A, const float* __restrict__ Bm,
    const float* __restrict__ bias, float* __restrict__ C,
    int M, int N, int K, int lda, int ldb, int ldc,
    long strA, long strB, long strC, float alpha, int flags)
{
    __shared__ uint32_t sA[16 * SAS];
    __shared__ uint32_t sB[16 * SAS];

    int z = blockIdx.z;
    A  += (long)z * strA;
    Bm += (long)z * strB;
    C  += (long)z * strC;
    int m0 = blockIdx.y * 128, n0 = blockIdx.x * 128;
    int tid = threadIdx.x;
    int warp = tid >> 5, lane = tid & 31;
    int wm = warp >> 1, wn = warp & 1;
    int g = lane >> 2, t = lane & 3;
    const bool transB = (flags & 1);

    float acc[2][8][4];
#pragma unroll
    for (int mt = 0; mt < 2; mt++)
#pragma unroll
        for (int nt = 0; nt < 8; nt++)
#pragma unroll
            for (int q = 0; q < 4; q++) acc[mt][nt][q] = 0.f;

    float4 rA[2], rB[2];
    const int nk = K >> 4;   // all K are multiples of 16

    // per-thread load coordinates (two 512-wide passes)
    int arow[2], akc[2], bkk[2], bnc[2];
#pragma unroll
    for (int it = 0; it < 2; it++) {
        int idx = tid + it * 256;
        arow[it] = idx >> 2;           // 0..127
        akc[it]  = (idx & 3) << 2;     // 0,4,8,12
        bkk[it]  = idx >> 5;           // 0..15   (NN layout)
        bnc[it]  = (idx & 31) << 2;    // 0..124
    }

    // prefetch tile 0
#pragma unroll
    for (int it = 0; it < 2; it++) {
        rA[it] = make_float4(0.f, 0.f, 0.f, 0.f);
        if (m0 + arow[it] < M)
            rA[it] = *(const float4*)&A[(long)(m0 + arow[it]) * lda + akc[it]];
        rB[it] = make_float4(0.f, 0.f, 0.f, 0.f);
        if (transB) {
            if (n0 + arow[it] < N)
                rB[it] = *(const float4*)&Bm[(long)(n0 + arow[it]) * ldb + akc[it]];
        } else {
            if (n0 + bnc[it] < N)
                rB[it] = *(const float4*)&Bm[(long)bkk[it] * ldb + n0 + bnc[it]];
        }
    }

    for (int kt = 0; kt < nk; kt++) {
        // store regs -> smem (with tf32 convert)
#pragma unroll
        for (int it = 0; it < 2; it++) {
            int r = arow[it], kc = akc[it];
            sA[(kc + 0) * SAS + r] = f2tf32(rA[it].x);
            sA[(kc + 1) * SAS + r] = f2tf32(rA[it].y);
            sA[(kc + 2) * SAS + r] = f2tf32(rA[it].z);
            sA[(kc + 3) * SAS + r] = f2tf32(rA[it].w);
            if (transB) {
                sB[(kc + 0) * SAS + r] = f2tf32(rB[it].x);
                sB[(kc + 1) * SAS + r] = f2tf32(rB[it].y);
                sB[(kc + 2) * SAS + r] = f2tf32(rB[it].z);
                sB[(kc + 3) * SAS + r] = f2tf32(rB[it].w);
            } else {
                int kk = bkk[it], nc = bnc[it];
                sB[kk * SAS + nc + 0] = f2tf32(rB[it].x);
                sB[kk * SAS + nc + 1] = f2tf32(rB[it].y);
                sB[kk * SAS + nc + 2] = f2tf32(rB[it].z);
                sB[kk * SAS + nc + 3] = f2tf32(rB[it].w);
            }
        }
        __syncthreads();

        // prefetch next tile (overlaps with the MMA work below)
        if (kt + 1 < nk) {
            long koff = (long)(kt + 1) << 4;
#pragma unroll
            for (int it = 0; it < 2; it++) {
                rA[it] = make_float4(0.f, 0.f, 0.f, 0.f);
                if (m0 + arow[it] < M)
                    rA[it] = *(const float4*)&A[(long)(m0 + arow[it]) * lda + koff + akc[it]];
                rB[it] = make_float4(0.f, 0.f, 0.f, 0.f);
                if (transB) {
                    if (n0 + arow[it] < N)
                        rB[it] = *(const float4*)&Bm[(long)(n0 + arow[it]) * ldb + koff + akc[it]];
                } else {
                    if (n0 + bnc[it] < N)
                        rB[it] = *(const float4*)&Bm[(long)(koff + bkk[it]) * ldb + n0 + bnc[it]];
                }
            }
        }

        // compute: 2 k-steps of 8
#pragma unroll
        for (int ks = 0; ks < 2; ks++) {
            int k0 = ks * 8;
            uint32_t aF[2][4];
#pragma unroll
            for (int mt = 0; mt < 2; mt++) {
                int rb = wm * 32 + mt * 16;
                aF[mt][0] = sA[(k0 + t) * SAS + rb + g];
                aF[mt][1] = sA[(k0 + t) * SAS + rb + g + 8];
                aF[mt][2] = sA[(k0 + t + 4) * SAS + rb + g];
                aF[mt][3] = sA[(k0 + t + 4) * SAS + rb + g + 8];
            }
#pragma unroll
            for (int nt = 0; nt < 8; nt++) {
                int cb = wn * 64 + nt * 8;
                uint32_t b0 = sB[(k0 + t) * SAS + cb + g];
                uint32_t b1 = sB[(k0 + t + 4) * SAS + cb + g];
                mma_tf32(acc[0][nt], aF[0], b0, b1);
                mma_tf32(acc[1][nt], aF[1], b0, b1);
            }
        }
        __syncthreads();
    }

    // epilogue
    const bool relu = (flags & 2);
#pragma unroll
    for (int mt = 0; mt < 2; mt++) {
        int row0 = m0 + wm * 32 + mt * 16 + g;
        int row1 = row0 + 8;
#pragma unroll
        for (int nt = 0; nt < 8; nt++) {
            int col = n0 + wn * 64 + nt * 8 + t * 2;
            if (col >= N) continue;      // N is even, col is even -> col+1 < N too
            float b0 = 0.f, b1 = 0.f;
            if (bias) { b0 = bias[col]; b1 = bias[col + 1]; }
            if (row0 < M) {
                float v0 = acc[mt][nt][0] * alpha + b0;
                float v1 = acc[mt][nt][1] * alpha + b1;
                if (relu) { v0 = fmaxf(v0, 0.f); v1 = fmaxf(v1, 0.f); }
                *(float2*)&C[(long)row0 * ldc + col] = make_float2(v0, v1);
            }
            if (row1 < M) {
                float v0 = acc[mt][nt][2] * alpha + b0;
                float v1 = acc[mt][nt][3] * alpha + b1;
                if (relu) { v0 = fmaxf(v0, 0.f); v1 = fmaxf(v1, 0.f); }
                *(float2*)&C[(long)row1 * ldc + col] = make_float2(v0, v1);
            }
        }
    }
}

// ---------------- transposes -------------------------------------------------
__global__ __launch_bounds__(256) void to_bhld_kernel(
    const float* __restrict__ in, float* __restrict__ out, int ld_in, int col0)
{
    long i = (long)blockIdx.x * 256 + threadIdx.x;
    if (i >= (long)Bv * Hv * Lv * DHv) return;
    int d = (int)(i & 63);
    long r = i >> 6;
    int l = (int)(r % Lv); r /= Lv;
    int h = (int)(r % Hv);
    int b = (int)(r / Hv);
    out[i] = in[((long)b * Lv + l) * ld_in + col0 + h * DHv + d];
}

__global__ __launch_bounds__(256) void from_bhld_kernel(
    const float* __restrict__ in, float* __restrict__ out)
{
    long i = (long)blockIdx.x * 256 + threadIdx.x;
    if (i >= (long)Bv * Lv * Dv) return;
    int d = (int)(i & 63);
    long r = i >> 6;
    int h = (int)(r & 7); r >>= 3;
    int l = (int)(r % Lv);
    int b = (int)(r / Lv);
    out[i] = in[(((long)b * Hv + h) * Lv + l) * DHv + d];
}

// ---------------- softmax ------------------------------------------------------
__global__ __launch_bounds__(256) void softmax_kernel(float* __restrict__ att)
{
    long row = blockIdx.x;
    float* p = att + row * (long)Lv;
    int tid = threadIdx.x;
    float vals[5];
    int cnt = 0;
    float mx = -1e30f;
    for (int c = tid; c < Lv; c += 256) { vals[cnt] = p[c]; mx = fmaxf(mx, vals[cnt]); cnt++; }
    __shared__ float red[256];
    red[tid] = mx; __syncthreads();
#pragma unroll
    for (int s = 128; s > 0; s >>= 1) { if (tid < s) red[tid] = fmaxf(red[tid], red[tid + s]); __syncthreads(); }
    mx = red[0]; __syncthreads();
    float sum = 0.f;
    for (int i = 0; i < cnt; i++) { vals[i] = expf(vals[i] - mx); sum += vals[i]; }
    red[tid] = sum; __syncthreads();
#pragma unroll
    for (int s = 128; s > 0; s >>= 1) { if (tid < s) red[tid] += red[tid + s]; __syncthreads(); }
    float inv = 1.f / red[0];
    cnt = 0;
    for (int c = tid; c < Lv; c += 256) { p[c] = vals[cnt] * inv; cnt++; }
}

// ---------------- residual + LayerNorm ----------------------------------------
__global__ __launch_bounds__(256) void ln_kernel(
    float* __restrict__ X, const float* __restrict__ Y,
    const float* __restrict__ g, const float* __restrict__ b)
{
    long row = blockIdx.x;
    float* x = X + row * (long)Dv;
    const float* y = Y + row * (long)Dv;
    int tid = threadIdx.x;
    float v0 = x[tid] + y[tid];
    float v1 = x[tid + 256] + y[tid + 256];
    __shared__ float red[256];
    red[tid] = v0 + v1; __syncthreads();
#pragma unroll
    for (int s = 128; s > 0; s >>= 1) { if (tid < s) red[tid] += red[tid + s]; __syncthreads(); }
    float mu = red[0] * (1.f / Dv); __syncthreads();
    float d0 = v0 - mu, d1 = v1 - mu;
    red[tid] = d0 * d0 + d1 * d1; __syncthreads();
#pragma unroll
    for (int s = 128; s > 0; s >>= 1) { if (tid < s) red[tid] += red[tid + s]; __syncthreads(); }
    float rstd = rsqrtf(red[0] * (1.f / Dv) + 1e-5f);
    x[tid]       = d0 * rstd * g[tid]       + b[tid];
    x[tid + 256] = d1 * rstd * g[tid + 256] + b[tid + 256];
}

// ---------------- host orchestration -----------------------------------------
static inline dim3 ggrid(int M, int N, int batch) {
    return dim3((N + 127) / 128, (M + 127) / 128, batch);
}

extern "C" void kernel_launch(void* const* d_in, const int* in_sizes, int n_in,
                              void* d_out, int out_size)
{
    const int*   token  = (const int*)  d_in[0];
    const int*   state  = (const int*)  d_in[1];
    const float* prefix = (const float*)d_in[2];
    const float* emb    = (const float*)d_in[3];
    const float* b_in   = (const float*)d_in[4];
    const float* pos    = (const float*)d_in[5];
    const float* W_out  = (const float*)d_in[6];
    const float* b_out  = (const float*)d_in[7];
    const float* qkv_w  = (const float*)d_in[8];
    const float* qkv_b  = (const float*)d_in[9];
    const float* out_w  = (const float*)d_in[10];
    const float* out_b  = (const float*)d_in[11];
    const float* lin1_w = (const float*)d_in[12];
    const float* lin1_b = (const float*)d_in[13];
    const float* lin2_w = (const float*)d_in[14];
    const float* lin2_b = (const float*)d_in[15];
    const float* ln_g   = (const float*)d_in[16];
    const float* ln_b   = (const float*)d_in[17];
    float* out = (float*)d_out;

    float *X, *MEM, *Q, *KV, *Qt, *Kt, *Vt, *att, *ctxT, *ctx, *Y, *Hff;
    cudaGetSymbolAddress((void**)&X,   g_X);
    cudaGetSymbolAddress((void**)&MEM, g_MEM);
    cudaGetSymbolAddress((void**)&Q,   g_Q);
    cudaGetSymbolAddress((void**)&KV,  g_KV);
    cudaGetSymbolAddress((void**)&Qt,  g_Qt);
    cudaGetSymbolAddress((void**)&Kt,  g_Kt);
    cudaGetSymbolAddress((void**)&Vt,  g_Vt);
    cudaGetSymbolAddress((void**)&att, g_att);
    cudaGetSymbolAddress((void**)&ctxT,g_ctxT);
    cudaGetSymbolAddress((void**)&ctx, g_ctx);
    cudaGetSymbolAddress((void**)&Y,   g_Y);
    cudaGetSymbolAddress((void**)&Hff, g_Hff);

    const int BL = Bv * Lv;
    const long nEmb = (long)Bv * Lv * Dv;
    const long nHead = (long)Bv * Hv * Lv * DHv;

    embed_kernel<<<(int)((nEmb + 255) / 256), 256>>>(token, state, prefix, emb, b_in, pos, X, MEM);

    const float scale = 1.f / 8.f;

    for (int i = 0; i < NLv; i++) {
        for (int j = 0; j < 2; j++) {
            const float* kvsrc = (j == 0) ? X : MEM;
            const float* w  = qkv_w + (long)(i * 2 + j) * 3 * Dv * Dv;
            const float* bb = qkv_b + (long)(i * 2 + j) * 3 * Dv;

            gemm_tf32_kernel<<<ggrid(BL, Dv, 1), 256>>>(X, w, bb, Q,
                BL, Dv, Dv, Dv, Dv, Dv, 0, 0, 0, 1.f, 1);
            gemm_tf32_kernel<<<ggrid(BL, 2 * Dv, 1), 256>>>(kvsrc, w + (long)Dv * Dv, bb + Dv, KV,
                BL, 2 * Dv, Dv, Dv, Dv, 2 * Dv, 0, 0, 0, 1.f, 1);

            to_bhld_kernel<<<(int)((nHead + 255) / 256), 256>>>(Q,  Qt, Dv, 0);
            to_bhld_kernel<<<(int)((nHead + 255) / 256), 256>>>(KV, Kt, 2 * Dv, 0);
            to_bhld_kernel<<<(int)((nHead + 255) / 256), 256>>>(KV, Vt, 2 * Dv, Dv);

            gemm_tf32_kernel<<<ggrid(Lv, Lv, Bv * Hv), 256>>>(Qt, Kt, nullptr, att,
                Lv, Lv, DHv, DHv, DHv, Lv,
                (long)Lv * DHv, (long)Lv * DHv, (long)Lv * Lv, scale, 1);

            softmax_kernel<<<Bv * Hv * Lv, 256>>>(att);

            gemm_tf32_kernel<<<ggrid(Lv, DHv, Bv * Hv), 256>>>(att, Vt, nullptr, ctxT,
                Lv, DHv, Lv, Lv, DHv, DHv,
                (long)Lv * Lv, (long)Lv * DHv, (long)Lv * DHv, 1.f, 0);

            from_bhld_kernel<<<(int)((nEmb + 255) / 256), 256>>>(ctxT, ctx);

            gemm_tf32_kernel<<<ggrid(BL, Dv, 1), 256>>>(ctx,
                out_w + (long)(i * 2 + j) * Dv * Dv, out_b + (long)(i * 2 + j) * Dv, Y,
                BL, Dv, Dv, Dv, Dv, Dv, 0, 0, 0, 1.f, 1);

            ln_kernel<<<BL, 256>>>(X, Y,
                ln_g + (long)(i * 3 + j) * Dv, ln_b + (long)(i * 3 + j) * Dv);
        }
        gemm_tf32_kernel<<<ggrid(BL, DFFv, 1), 256>>>(X,
            lin1_w + (long)i * DFFv * Dv, lin1_b + (long)i * DFFv, Hff,
            BL, DFFv, Dv, Dv, Dv, DFFv, 0, 0, 0, 1.f, 1 | 2);
        gemm_tf32_kernel<<<ggrid(BL, Dv, 1), 256>>>(Hff,
            lin2_w + (long)i * Dv * DFFv, lin2_b + (long)i * Dv, Y,
            BL, Dv, DFFv, DFFv, DFFv, Dv, 0, 0, 0, 1.f, 1);
        ln_kernel<<<BL, 256>>>(X, Y,
            ln_g + (long)(i * 3 + 2) * Dv, ln_b + (long)(i * 3 + 2) * Dv);
    }

    gemm_tf32_kernel<<<ggrid(Tv, VSv, Bv), 256>>>(X + (long)Cv * Dv, W_out, b_out, out,
        Tv, VSv, Dv, Dv, Dv, VSv,
        (long)Lv * Dv, 0, (long)Tv * VSv, 1.f, 1);
}

// round 4
// speedup vs baseline: 2.2152x; 1.0003x over previous
#include <cuda_runtime.h>
#include <cuda_bf16.h>
#include <math.h>
#include <stdint.h>

// Problem constants
#define Bv 8
#define Tv 1024
#define Cv 16
#define Lv 1040      // C + T
#define Dv 512
#define Hv 8
#define DHv 64
#define NLv 2
#define DFFv 2048
#define VSv 8000     // V*S
#define Sv 8

// ---------------- scratch (static device globals; allocation-free) ----------
__device__ float g_X  [Bv * Lv * Dv];
__device__ float g_MEM[Bv * Lv * Dv];
__device__ float g_Q  [Bv * Lv * Dv];
__device__ float g_KV [Bv * Lv * 2 * Dv];
__device__ float g_Qt [Bv * Hv * Lv * DHv];
__device__ float g_Kt [Bv * Hv * Lv * DHv];
__device__ float g_Vt [Bv * Hv * Lv * DHv];
__device__ float g_att[(long)Bv * Hv * Lv * Lv];
__device__ float g_ctxT[Bv * Hv * Lv * DHv];
__device__ float g_ctx[Bv * Lv * Dv];
__device__ float g_Y  [Bv * Lv * Dv];
__device__ float g_Hff[Bv * Lv * DFFv];

// ---------------- embed ------------------------------------------------------
__global__ __launch_bounds__(256) void embed_kernel(
    const int* __restrict__ token, const int* __restrict__ state,
    const float* __restrict__ prefix, const float* __restrict__ emb,
    const float* __restrict__ b_in, const float* __restrict__ pos,
    float* __restrict__ X, float* __restrict__ MEM)
{
    long i = (long)blockIdx.x * 256 + threadIdx.x;
    if (i >= (long)Bv * Lv * Dv) return;
    int d = (int)(i & (Dv - 1));
    long r = i >> 9;
    int l = (int)(r % Lv);
    int b = (int)(r / Lv);
    float v;
    if (l < Cv) {
        v = prefix[((long)b * Cv + l) * Dv + d];
    } else {
        int t = l - Cv;
        int row = token[b * Tv + t] * Sv + state[b];
        v = emb[(long)row * Dv + d] + b_in[d];
    }
    v += pos[(long)l * Dv + d];
    X[i] = v;
    MEM[i] = v;
}

// ---------------- tf32 tensor-core GEMM --------------------------------------
// C = alpha * A * op(B) + bias  ; A:[M,K] lda ; B: transB? [N,K]:[K,N] ldb
// flags: bit0 = transB ; bit1 = relu. Batched via element strides sA/sB/sC.
// Tile: BM=128, BN=128, BK=16. 256 threads = 8 warps (4 M x 2 N), warp = 32x64.
#define SAS 136   // smem row stride (conflict-free: (t*136+g)%32 hits 32 banks)

__device__ __forceinline__ uint32_t f2tf32(float x) {
    uint32_t r;
    asm("cvt.rna.tf32.f32 %0, %1;" : "=r"(r) : "f"(x));
    return r;
}

__device__ __forceinline__ void mma_tf32(float* d, const uint32_t* a,
                                         uint32_t b0, uint32_t b1) {
    asm volatile(
        "mma.sync.aligned.m16n8k8.row.col.f32.tf32.tf32.f32 "
        "{%0,%1,%2,%3}, {%4,%5,%6,%7}, {%8,%9}, {%0,%1,%2,%3};\n"
        : "+f"(d[0]), "+f"(d[1]), "+f"(d[2]), "+f"(d[3])
        : "r"(a[0]), "r"(a[1]), "r"(a[2]), "r"(a[3]), "r"(b0), "r"(b1));
}

__global__ __launch_bounds__(256) void gemm_tf32_kernel(
    const float* __restrict__ A, const float* __restrict__ Bm,
    const float* __restrict__ bias, float* __restrict__ C,
    int M, int N, int K, int lda, int ldb, int ldc,
    long strA, long strB, long strC, float alpha, int flags)
{
    __shared__ uint32_t sA[16 * SAS];
    __shared__ uint32_t sB[16 * SAS];

    int z = blockIdx.z;
    A  += (long)z * strA;
    Bm += (long)z * strB;
    C  += (long)z * strC;
    int m0 = blockIdx.y * 128, n0 = blockIdx.x * 128;
    int tid = threadIdx.x;
    int warp = tid >> 5, lane = tid & 31;
    int wm = warp >> 1, wn = warp & 1;
    int g = lane >> 2, t = lane & 3;
    const bool transB = (flags & 1);

    float acc[2][8][4];
#pragma unroll
    for (int mt = 0; mt < 2; mt++)
#pragma unroll
        for (int nt = 0; nt < 8; nt++)
#pragma unroll
            for (int q = 0; q < 4; q++) acc[mt][nt][q] = 0.f;

    float4 rA[2], rB[2];
    const int nk = K >> 4;   // all K are multiples of 16

    // per-thread load coordinates (two 512-wide passes)
    int arow[2], akc[2], bkk[2], bnc[2];
#pragma unroll
    for (int it = 0; it < 2; it++) {
        int idx = tid + it * 256;
        arow[it] = idx >> 2;           // 0..127
        akc[it]  = (idx & 3) << 2;     // 0,4,8,12
        bkk[it]  = idx >> 5;           // 0..15   (NN layout)
        bnc[it]  = (idx & 31) << 2;    // 0..124
    }

    // prefetch tile 0
#pragma unroll
    for (int it = 0; it < 2; it++) {
        rA[it] = make_float4(0.f, 0.f, 0.f, 0.f);
        if (m0 + arow[it] < M)
            rA[it] = *(const float4*)&A[(long)(m0 + arow[it]) * lda + akc[it]];
        rB[it] = make_float4(0.f, 0.f, 0.f, 0.f);
        if (transB) {
            if (n0 + arow[it] < N)
                rB[it] = *(const float4*)&Bm[(long)(n0 + arow[it]) * ldb + akc[it]];
        } else {
            if (n0 + bnc[it] < N)
                rB[it] = *(const float4*)&Bm[(long)bkk[it] * ldb + n0 + bnc[it]];
        }
    }

    for (int kt = 0; kt < nk; kt++) {
        // store regs -> smem (with tf32 convert)
#pragma unroll
        for (int it = 0; it < 2; it++) {
            int r = arow[it], kc = akc[it];
            sA[(kc + 0) * SAS + r] = f2tf32(rA[it].x);
            sA[(kc + 1) * SAS + r] = f2tf32(rA[it].y);
            sA[(kc + 2) * SAS + r] = f2tf32(rA[it].z);
            sA[(kc + 3) * SAS + r] = f2tf32(rA[it].w);
            if (transB) {
                sB[(kc + 0) * SAS + r] = f2tf32(rB[it].x);
                sB[(kc + 1) * SAS + r] = f2tf32(rB[it].y);
                sB[(kc + 2) * SAS + r] = f2tf32(rB[it].z);
                sB[(kc + 3) * SAS + r] = f2tf32(rB[it].w);
            } else {
                int kk = bkk[it], nc = bnc[it];
                sB[kk * SAS + nc + 0] = f2tf32(rB[it].x);
                sB[kk * SAS + nc + 1] = f2tf32(rB[it].y);
                sB[kk * SAS + nc + 2] = f2tf32(rB[it].z);
                sB[kk * SAS + nc + 3] = f2tf32(rB[it].w);
            }
        }
        __syncthreads();

        // prefetch next tile (overlaps with the MMA work below)
        if (kt + 1 < nk) {
            long koff = (long)(kt + 1) << 4;
#pragma unroll
            for (int it = 0; it < 2; it++) {
                rA[it] = make_float4(0.f, 0.f, 0.f, 0.f);
                if (m0 + arow[it] < M)
                    rA[it] = *(const float4*)&A[(long)(m0 + arow[it]) * lda + koff + akc[it]];
                rB[it] = make_float4(0.f, 0.f, 0.f, 0.f);
                if (transB) {
                    if (n0 + arow[it] < N)
                        rB[it] = *(const float4*)&Bm[(long)(n0 + arow[it]) * ldb + koff + akc[it]];
                } else {
                    if (n0 + bnc[it] < N)
                        rB[it] = *(const float4*)&Bm[(long)(koff + bkk[it]) * ldb + n0 + bnc[it]];
                }
            }
        }

        // compute: 2 k-steps of 8
#pragma unroll
        for (int ks = 0; ks < 2; ks++) {
            int k0 = ks * 8;
            uint32_t aF[2][4];
#pragma unroll
            for (int mt = 0; mt < 2; mt++) {
                int rb = wm * 32 + mt * 16;
                aF[mt][0] = sA[(k0 + t) * SAS + rb + g];
                aF[mt][1] = sA[(k0 + t) * SAS + rb + g + 8];
                aF[mt][2] = sA[(k0 + t + 4) * SAS + rb + g];
                aF[mt][3] = sA[(k0 + t + 4) * SAS + rb + g + 8];
            }
#pragma unroll
            for (int nt = 0; nt < 8; nt++) {
                int cb = wn * 64 + nt * 8;
                uint32_t b0 = sB[(k0 + t) * SAS + cb + g];
                uint32_t b1 = sB[(k0 + t + 4) * SAS + cb + g];
                mma_tf32(acc[0][nt], aF[0], b0, b1);
                mma_tf32(acc[1][nt], aF[1], b0, b1);
            }
        }
        __syncthreads();
    }

    // epilogue
    const bool relu = (flags & 2);
#pragma unroll
    for (int mt = 0; mt < 2; mt++) {
        int row0 = m0 + wm * 32 + mt * 16 + g;
        int row1 = row0 + 8;
#pragma unroll
        for (int nt = 0; nt < 8; nt++) {
            int col = n0 + wn * 64 + nt * 8 + t * 2;
            if (col >= N) continue;      // N is even, col is even -> col+1 < N too
            float b0 = 0.f, b1 = 0.f;
            if (bias) { b0 = bias[col]; b1 = bias[col + 1]; }
            if (row0 < M) {
                float v0 = acc[mt][nt][0] * alpha + b0;
                float v1 = acc[mt][nt][1] * alpha + b1;
                if (relu) { v0 = fmaxf(v0, 0.f); v1 = fmaxf(v1, 0.f); }
                *(float2*)&C[(long)row0 * ldc + col] = make_float2(v0, v1);
            }
            if (row1 < M) {
                float v0 = acc[mt][nt][2] * alpha + b0;
                float v1 = acc[mt][nt][3] * alpha + b1;
                if (relu) { v0 = fmaxf(v0, 0.f); v1 = fmaxf(v1, 0.f); }
                *(float2*)&C[(long)row1 * ldc + col] = make_float2(v0, v1);
            }
        }
    }
}

// ---------------- transposes -------------------------------------------------
__global__ __launch_bounds__(256) void to_bhld_kernel(
    const float* __restrict__ in, float* __restrict__ out, int ld_in, int col0)
{
    long i = (long)blockIdx.x * 256 + threadIdx.x;
    if (i >= (long)Bv * Hv * Lv * DHv) return;
    int d = (int)(i & 63);
    long r = i >> 6;
    int l = (int)(r % Lv); r /= Lv;
    int h = (int)(r % Hv);
    int b = (int)(r / Hv);
    out[i] = in[((long)b * Lv + l) * ld_in + col0 + h * DHv + d];
}

__global__ __launch_bounds__(256) void from_bhld_kernel(
    const float* __restrict__ in, float* __restrict__ out)
{
    long i = (long)blockIdx.x * 256 + threadIdx.x;
    if (i >= (long)Bv * Lv * Dv) return;
    int d = (int)(i & 63);
    long r = i >> 6;
    int h = (int)(r & 7); r >>= 3;
    int l = (int)(r % Lv);
    int b = (int)(r / Lv);
    out[i] = in[(((long)b * Hv + h) * Lv + l) * DHv + d];
}

// ---------------- softmax ------------------------------------------------------
__global__ __launch_bounds__(256) void softmax_kernel(float* __restrict__ att)
{
    long row = blockIdx.x;
    float* p = att + row * (long)Lv;
    int tid = threadIdx.x;
    float vals[5];
    int cnt = 0;
    float mx = -1e30f;
    for (int c = tid; c < Lv; c += 256) { vals[cnt] = p[c]; mx = fmaxf(mx, vals[cnt]); cnt++; }
    __shared__ float red[256];
    red[tid] = mx; __syncthreads();
#pragma unroll
    for (int s = 128; s > 0; s >>= 1) { if (tid < s) red[tid] = fmaxf(red[tid], red[tid + s]); __syncthreads(); }
    mx = red[0]; __syncthreads();
    float sum = 0.f;
    for (int i = 0; i < cnt; i++) { vals[i] = expf(vals[i] - mx); sum += vals[i]; }
    red[tid] = sum; __syncthreads();
#pragma unroll
    for (int s = 128; s > 0; s >>= 1) { if (tid < s) red[tid] += red[tid + s]; __syncthreads(); }
    float inv = 1.f / red[0];
    cnt = 0;
    for (int c = tid; c < Lv; c += 256) { p[c] = vals[cnt] * inv; cnt++; }
}

// ---------------- residual + LayerNorm ----------------------------------------
__global__ __launch_bounds__(256) void ln_kernel(
    float* __restrict__ X, const float* __restrict__ Y,
    const float* __restrict__ g, const float* __restrict__ b)
{
    long row = blockIdx.x;
    float* x = X + row * (long)Dv;
    const float* y = Y + row * (long)Dv;
    int tid = threadIdx.x;
    float v0 = x[tid] + y[tid];
    float v1 = x[tid + 256] + y[tid + 256];
    __shared__ float red[256];
    red[tid] = v0 + v1; __syncthreads();
#pragma unroll
    for (int s = 128; s > 0; s >>= 1) { if (tid < s) red[tid] += red[tid + s]; __syncthreads(); }
    float mu = red[0] * (1.f / Dv); __syncthreads();
    float d0 = v0 - mu, d1 = v1 - mu;
    red[tid] = d0 * d0 + d1 * d1; __syncthreads();
#pragma unroll
    for (int s = 128; s > 0; s >>= 1) { if (tid < s) red[tid] += red[tid + s]; __syncthreads(); }
    float rstd = rsqrtf(red[0] * (1.f / Dv) + 1e-5f);
    x[tid]       = d0 * rstd * g[tid]       + b[tid];
    x[tid + 256] = d1 * rstd * g[tid + 256] + b[tid + 256];
}

// ---------------- host orchestration -----------------------------------------
static inline dim3 ggrid(int M, int N, int batch) {
    return dim3((N + 127) / 128, (M + 127) / 128, batch);
}

extern "C" void kernel_launch(void* const* d_in, const int* in_sizes, int n_in,
                              void* d_out, int out_size)
{
    const int*   token  = (const int*)  d_in[0];
    const int*   state  = (const int*)  d_in[1];
    const float* prefix = (const float*)d_in[2];
    const float* emb    = (const float*)d_in[3];
    const float* b_in   = (const float*)d_in[4];
    const float* pos    = (const float*)d_in[5];
    const float* W_out  = (const float*)d_in[6];
    const float* b_out  = (const float*)d_in[7];
    const float* qkv_w  = (const float*)d_in[8];
    const float* qkv_b  = (const float*)d_in[9];
    const float* out_w  = (const float*)d_in[10];
    const float* out_b  = (const float*)d_in[11];
    const float* lin1_w = (const float*)d_in[12];
    const float* lin1_b = (const float*)d_in[13];
    const float* lin2_w = (const float*)d_in[14];
    const float* lin2_b = (const float*)d_in[15];
    const float* ln_g   = (const float*)d_in[16];
    const float* ln_b   = (const float*)d_in[17];
    float* out = (float*)d_out;

    float *X, *MEM, *Q, *KV, *Qt, *Kt, *Vt, *att, *ctxT, *ctx, *Y, *Hff;
    cudaGetSymbolAddress((void**)&X,   g_X);
    cudaGetSymbolAddress((void**)&MEM, g_MEM);
    cudaGetSymbolAddress((void**)&Q,   g_Q);
    cudaGetSymbolAddress((void**)&KV,  g_KV);
    cudaGetSymbolAddress((void**)&Qt,  g_Qt);
    cudaGetSymbolAddress((void**)&Kt,  g_Kt);
    cudaGetSymbolAddress((void**)&Vt,  g_Vt);
    cudaGetSymbolAddress((void**)&att, g_att);
    cudaGetSymbolAddress((void**)&ctxT,g_ctxT);
    cudaGetSymbolAddress((void**)&ctx, g_ctx);
    cudaGetSymbolAddress((void**)&Y,   g_Y);
    cudaGetSymbolAddress((void**)&Hff, g_Hff);

    const int BL = Bv * Lv;
    const long nEmb = (long)Bv * Lv * Dv;
    const long nHead = (long)Bv * Hv * Lv * DHv;

    embed_kernel<<<(int)((nEmb + 255) / 256), 256>>>(token, state, prefix, emb, b_in, pos, X, MEM);

    const float scale = 1.f / 8.f;

    for (int i = 0; i < NLv; i++) {
        for (int j = 0; j < 2; j++) {
            const float* kvsrc = (j == 0) ? X : MEM;
            const float* w  = qkv_w + (long)(i * 2 + j) * 3 * Dv * Dv;
            const float* bb = qkv_b + (long)(i * 2 + j) * 3 * Dv;

            gemm_tf32_kernel<<<ggrid(BL, Dv, 1), 256>>>(X, w, bb, Q,
                BL, Dv, Dv, Dv, Dv, Dv, 0, 0, 0, 1.f, 1);
            gemm_tf32_kernel<<<ggrid(BL, 2 * Dv, 1), 256>>>(kvsrc, w + (long)Dv * Dv, bb + Dv, KV,
                BL, 2 * Dv, Dv, Dv, Dv, 2 * Dv, 0, 0, 0, 1.f, 1);

            to_bhld_kernel<<<(int)((nHead + 255) / 256), 256>>>(Q,  Qt, Dv, 0);
            to_bhld_kernel<<<(int)((nHead + 255) / 256), 256>>>(KV, Kt, 2 * Dv, 0);
            to_bhld_kernel<<<(int)((nHead + 255) / 256), 256>>>(KV, Vt, 2 * Dv, Dv);

            gemm_tf32_kernel<<<ggrid(Lv, Lv, Bv * Hv), 256>>>(Qt, Kt, nullptr, att,
                Lv, Lv, DHv, DHv, DHv, Lv,
                (long)Lv * DHv, (long)Lv * DHv, (long)Lv * Lv, scale, 1);

            softmax_kernel<<<Bv * Hv * Lv, 256>>>(att);

            gemm_tf32_kernel<<<ggrid(Lv, DHv, Bv * Hv), 256>>>(att, Vt, nullptr, ctxT,
                Lv, DHv, Lv, Lv, DHv, DHv,
                (long)Lv * Lv, (long)Lv * DHv, (long)Lv * DHv, 1.f, 0);

            from_bhld_kernel<<<(int)((nEmb + 255) / 256), 256>>>(ctxT, ctx);

            gemm_tf32_kernel<<<ggrid(BL, Dv, 1), 256>>>(ctx,
                out_w + (long)(i * 2 + j) * Dv * Dv, out_b + (long)(i * 2 + j) * Dv, Y,
                BL, Dv, Dv, Dv, Dv, Dv, 0, 0, 0, 1.f, 1);

            ln_kernel<<<BL, 256>>>(X, Y,
                ln_g + (long)(i * 3 + j) * Dv, ln_b + (long)(i * 3 + j) * Dv);
        }
        gemm_tf32_kernel<<<ggrid(BL, DFFv, 1), 256>>>(X,
            lin1_w + (long)i * DFFv * Dv, lin1_b + (long)i * DFFv, Hff,
            BL, DFFv, Dv, Dv, Dv, DFFv, 0, 0, 0, 1.f, 1 | 2);
        gemm_tf32_kernel<<<ggrid(BL, Dv, 1), 256>>>(Hff,
            lin2_w + (long)i * Dv * DFFv, lin2_b + (long)i * Dv, Y,
            BL, Dv, DFFv, DFFv, DFFv, Dv, 0, 0, 0, 1.f, 1);
        ln_kernel<<<BL, 256>>>(X, Y,
            ln_g + (long)(i * 3 + 2) * Dv, ln_b + (long)(i * 3 + 2) * Dv);
    }

    gemm_tf32_kernel<<<ggrid(Tv, VSv, Bv), 256>>>(X + (long)Cv * Dv, W_out, b_out, out,
        Tv, VSv, Dv, Dv, Dv, VSv,
        (long)Lv * Dv, 0, (long)Tv * VSv, 1.f, 1);
}